// round 15
// baseline (speedup 1.0000x reference)
#include <cuda_runtime.h>
#include <cuda_bf16.h>

#define NZg    192
#define PLANEg (192 * 192)
#define VOLg   (192 * 192 * 192)

#define TYB     4                    // y rows per block
#define THREADS 384                  // 96 z-float2 groups x 4 y rows
#define SEG     32                   // x planes per block
#define NXSEG   (192 / SEG)          // 6
#define NYT     (192 / TYB)          // 48
#define NPART   (NYT * NXSEG * 2)    // 576 block partials
#define NVOX    14155776.0           // 2 * 192^3

typedef unsigned long long u64;

__device__ float        g_partials[NPART];
__device__ unsigned int g_count;     // zero at load; last block resets each launch

__device__ __forceinline__ float2 ld2(const float* __restrict__ p) {
    return *reinterpret_cast<const float2*>(p);
}
__device__ __forceinline__ void pfl1(const float* p) {
    asm volatile("prefetch.global.L1 [%0];" :: "l"(p));
}

// ---- packed f32x2 primitives ----
__device__ __forceinline__ u64 pk2(float lo, float hi) {
    u64 r; asm("mov.b64 %0, {%1, %2};" : "=l"(r) : "f"(lo), "f"(hi)); return r;
}
__device__ __forceinline__ void up2(u64 v, float& lo, float& hi) {
    asm("mov.b64 {%0, %1}, %2;" : "=f"(lo), "=f"(hi) : "l"(v));
}
__device__ __forceinline__ u64 add2_(u64 a, u64 b) {
    u64 r; asm("add.rn.f32x2 %0, %1, %2;" : "=l"(r) : "l"(a), "l"(b)); return r;
}
__device__ __forceinline__ u64 mul2_(u64 a, u64 b) {
    u64 r; asm("mul.rn.f32x2 %0, %1, %2;" : "=l"(r) : "l"(a), "l"(b)); return r;
}
__device__ __forceinline__ u64 fma2_(u64 a, u64 b, u64 c) {
    u64 r; asm("fma.rn.f32x2 %0, %1, %2, %3;" : "=l"(r) : "l"(a), "l"(b), "l"(c)); return r;
}

// Huber robust penalty, delta = 0.01 (select form; scalar on halves).
__device__ __forceinline__ float robustf(float x) {
    float ax = fabsf(x);
    return (ax <= 0.01f) ? 0.5f * x * x : 0.01f * (ax - 0.005f);
}

// Contribution of 2 voxels, all inputs packed f32x2. (Validated in R14.)
__device__ __forceinline__ u64 pair_contrib(
    u64 UX, u64 UY, u64 UZ,
    u64 VX, u64 VY, u64 VZ,
    u64 WX, u64 WY, u64 WZ)
{
    const u64 C_HALF = pk2(0.5f, 0.5f);
    const u64 C_ONE  = pk2(1.0f, 1.0f);
    const u64 C_NEG1 = pk2(-1.0f, -1.0f);
    const u64 C_TEN  = pk2(0.1f, 0.1f);

    u64 EXY = mul2_(add2_(UY, VX), C_HALF);
    u64 EXZ = mul2_(add2_(UZ, WX), C_HALF);
    u64 EYZ = mul2_(add2_(VZ, WY), C_HALF);
    u64 TR  = add2_(add2_(UX, VY), WZ);

    float t0, t1;
    up2(TR,  t0, t1); float rt0 = robustf(t0), rt1 = robustf(t1);
    up2(UX,  t0, t1); float ra0 = robustf(t0), ra1 = robustf(t1);
    up2(VY,  t0, t1); float rb0 = robustf(t0), rb1 = robustf(t1);
    up2(WZ,  t0, t1); float rc0 = robustf(t0), rc1 = robustf(t1);
    up2(EXY, t0, t1); float rd0 = robustf(t0), rd1 = robustf(t1);
    up2(EXZ, t0, t1); float re0 = robustf(t0), re1 = robustf(t1);
    up2(EYZ, t0, t1); float rf0 = robustf(t0), rf1 = robustf(t1);

    u64 RT = pk2(rt0, rt1), RA = pk2(ra0, ra1), RB = pk2(rb0, rb1), RC = pk2(rc0, rc1);
    u64 RD = pk2(rd0, rd1), RE = pk2(re0, re1), RF = pk2(rf0, rf1);

    // energy = 0.5*(rt^2 + rxx^2 + ryy^2 + rzz^2) + 1.0*(rxy^2 + rxz^2 + ryz^2)
    u64 Q1 = mul2_(RT, RT);
    Q1 = fma2_(RA, RA, Q1);
    Q1 = fma2_(RB, RB, Q1);
    Q1 = fma2_(RC, RC, Q1);
    u64 Q2 = mul2_(RD, RD);
    Q2 = fma2_(RE, RE, Q2);
    Q2 = fma2_(RF, RF, Q2);
    u64 EN = fma2_(Q1, C_HALF, Q2);

    // Jacobian exactly as written in the reference (NOT the textbook determinant).
    u64 P = add2_(UX, C_ONE);
    u64 Q = add2_(VY, C_ONE);
    u64 R = add2_(WZ, C_ONE);
    u64 S = add2_(WX, C_ONE);
    u64 M1 = fma2_(Q,  R,  mul2_(mul2_(VZ, WY), C_NEG1));
    u64 M2 = fma2_(VX, R,  mul2_(mul2_(VZ, S),  C_NEG1));
    u64 M3 = fma2_(VX, WY, mul2_(mul2_(Q,  S),  C_NEG1));
    u64 J  = mul2_(P, M1);
    J = fma2_(mul2_(UY, C_NEG1), M2, J);
    J = fma2_(UZ, M3, J);

    float j0, j1; up2(J, j0, j1);
    float p0 = fmaxf(-j0, 0.0f), p1 = fmaxf(-j1, 0.0f);
    return fma2_(pk2(p0, p1), C_TEN, EN);
}

// Stateless plane step for 2 z-voxels x 3 channels. All operands from L1
// (prefetched); a_is_c / n_is_c are literal at each call site (x boundaries).
__device__ __forceinline__ u64 step_plane(
    const float* __restrict__ pu, const float* __restrict__ pv,
    const float* __restrict__ pw,
    int dym, int dyp, int zq2, float sx, float sy,
    bool a_is_c, bool n_is_c, u64 acc2)
{
    const u64 NEG1 = pk2(-1.0f, -1.0f);
    const u64 SX2  = pk2(sx, sx);
    const u64 SY2  = pk2(sy, sy);
    const float* pc[3] = { pu, pv, pw };

    u64 GX[3], GY[3], GZ[3];
    #pragma unroll
    for (int ch = 0; ch < 3; ++ch) {
        const float* p = pc[ch];
        const float2 cv = ld2(p);
        const float2 av = a_is_c ? cv : ld2(p - PLANEg);
        const float2 nv = n_is_c ? cv : ld2(p + PLANEg);
        const float2 ym = ld2(p + dym);
        const float2 yp = ld2(p + dyp);
        const float  zm = (zq2 > 0)  ? p[-1] : 0.0f;
        const float  zp = (zq2 < 95) ? p[2]  : 0.0f;

        GX[ch] = mul2_(fma2_(pk2(av.x, av.y), NEG1, pk2(nv.x, nv.y)), SX2);
        GY[ch] = mul2_(fma2_(pk2(ym.x, ym.y), NEG1, pk2(yp.x, yp.y)), SY2);
        // z gradients: one-sided at z = 0 / z = 191 (both reduce to cv.y - cv.x)
        const float gz0 = (zq2 > 0)  ? (cv.y - zm) * 0.5f : (cv.y - cv.x);
        const float gz1 = (zq2 < 95) ? (zp - cv.x) * 0.5f : (cv.y - cv.x);
        GZ[ch] = pk2(gz0, gz1);
    }
    return add2_(acc2, pair_contrib(GX[0], GY[0], GZ[0],
                                    GX[1], GY[1], GZ[1],
                                    GX[2], GY[2], GZ[2]));
}

__global__ __launch_bounds__(THREADS, 3)
void elastic_march(const float* __restrict__ df, float* __restrict__ out)
{
    const int tid = threadIdx.x;
    const int zq2 = tid % 96;                 // z float2 group, z0 = 2*zq2
    const int yy  = tid / 96;                 // 0..3
    const int y   = blockIdx.x * TYB + yy;    // 0..191
    const int xs  = blockIdx.y * SEG;
    const int b   = blockIdx.z;
    const bool first = (blockIdx.y == 0);
    const bool last  = (blockIdx.y == NXSEG - 1);

    const float sy  = (y > 0 && y < 191) ? 0.5f : 1.0f;
    const int   dym = (y > 0)   ? -NZg : 0;
    const int   dyp = (y < 191) ?  NZg : 0;

    const float* __restrict__ p0 =
        df + (size_t)b * 3 * VOLg + (size_t)xs * PLANEg + (size_t)y * NZg + 2 * zq2;
    const float* pu = p0;
    const float* pv = p0 + VOLg;
    const float* pw = p0 + 2 * VOLg;

    // ---- warmup prefetch: planes xs-1 (if any), xs, xs+1, xs+2 ----
    if (!first) { pfl1(pu - PLANEg); pfl1(pv - PLANEg); pfl1(pw - PLANEg); }
    pfl1(pu);              pfl1(pv);              pfl1(pw);
    pfl1(pu + PLANEg);     pfl1(pv + PLANEg);     pfl1(pw + PLANEg);
    pfl1(pu + 2 * PLANEg); pfl1(pv + 2 * PLANEg); pfl1(pw + 2 * PLANEg);

    u64 acc2 = pk2(0.0f, 0.0f);
    int x = xs;

    // ---- prologue: x = 0 (first segment only): a == c, sx = 1 ----
    if (first) {
        acc2 = step_plane(pu, pv, pw, dym, dyp, zq2, 1.0f, sy, true, false, acc2);
        pu += PLANEg; pv += PLANEg; pw += PLANEg;
        x = 1;
    }

    // ---- interior: sx = 0.5 literal; prefetch x+2 (max 191) ----
    const int x_hi = last ? 190 : xs + SEG;
    #pragma unroll 1
    for (; x < x_hi; ++x) {
        pfl1(pu + 2 * PLANEg); pfl1(pv + 2 * PLANEg); pfl1(pw + 2 * PLANEg);
        acc2 = step_plane(pu, pv, pw, dym, dyp, zq2, 0.5f, sy, false, false, acc2);
        pu += PLANEg; pv += PLANEg; pw += PLANEg;
    }

    if (last) {
        // x = 190: no prefetch needed
        acc2 = step_plane(pu, pv, pw, dym, dyp, zq2, 0.5f, sy, false, false, acc2);
        pu += PLANEg; pv += PLANEg; pw += PLANEg;
        // x = 191: n == c, sx = 1
        acc2 = step_plane(pu, pv, pw, dym, dyp, zq2, 1.0f, sy, false, true, acc2);
    }

    float a0, a1;
    up2(acc2, a0, a1);
    float acc = a0 + a1;

    // ---- block reduction: warp shuffle -> shared -> warp 0 ----
    __shared__ float  swarp[32];
    __shared__ bool   s_last;
    __shared__ double sdw[32];

    const int lane = tid & 31;
    const int wid  = tid >> 5;                 // 12 warps

    #pragma unroll
    for (int o = 16; o > 0; o >>= 1)
        acc += __shfl_xor_sync(0xffffffffu, acc, o);
    if (lane == 0) swarp[wid] = acc;
    __syncthreads();

    if (tid < 32) {
        float v = (tid < THREADS / 32) ? swarp[tid] : 0.0f;
        #pragma unroll
        for (int o = 16; o > 0; o >>= 1)
            v += __shfl_xor_sync(0xffffffffu, v, o);
        if (tid == 0) {
            const int bid = blockIdx.x + NYT * (blockIdx.y + NXSEG * blockIdx.z);
            g_partials[bid] = v;
            __threadfence();
            unsigned old = atomicAdd(&g_count, 1u);
            s_last = (old == NPART - 1);
        }
    }
    __syncthreads();

    // ---- last block: deterministic final sum in double ----
    if (s_last) {
        double d = (double)__ldcg(&g_partials[tid]);
        if (tid < NPART - THREADS)                 // 576 partials, 384 threads
            d += (double)__ldcg(&g_partials[tid + THREADS]);
        #pragma unroll
        for (int o = 16; o > 0; o >>= 1)
            d += __shfl_xor_sync(0xffffffffu, d, o);
        if (lane == 0) sdw[wid] = d;
        __syncthreads();
        if (tid < 32) {
            double v = (tid < THREADS / 32) ? sdw[tid] : 0.0;
            #pragma unroll
            for (int o = 16; o > 0; o >>= 1)
                v += __shfl_xor_sync(0xffffffffu, v, o);
            if (tid == 0) {
                g_count = 0;                       // reset for graph replay
                out[0] = (float)(v / NVOX);
            }
        }
    }
}

extern "C" void kernel_launch(void* const* d_in, const int* in_sizes, int n_in,
                              void* d_out, int out_size) {
    const float* df = (const float*)d_in[0];
    dim3 grid(NYT, NXSEG, 2);   // 48 x 6 x 2 = 576 blocks, 3/SM resident
    elastic_march<<<grid, THREADS>>>(df, (float*)d_out);
}

// round 16
// speedup vs baseline: 1.4725x; 1.4725x over previous
#include <cuda_runtime.h>
#include <cuda_bf16.h>

#define NZg    192
#define PLANEg (192 * 192)
#define VOLg   (192 * 192 * 192)

#define TYB     8                    // y rows per block
#define THREADS (48 * TYB)           // 384
#define SEG     32                   // x planes per block
#define NXSEG   (192 / SEG)          // 6
#define NYT     (192 / TYB)          // 24
#define NPART   (NYT * NXSEG * 2)    // 288 block partials
#define NVOX    14155776.0           // 2 * 192^3

__device__ float        g_partials[NPART];
__device__ unsigned int g_count;     // zero at load; last block resets each launch

__device__ __forceinline__ float4 ld4(const float* __restrict__ p) {
    return *reinterpret_cast<const float4*>(p);
}

// s(x) = x^2 - relu(|x|-d)^2  =>  robust(x)^2 == 0.25 * s(x)^2  (exact identity:
// robust(x) = 0.5x^2 - 0.5*relu(|x|-d)^2). Branch-free: FADD+FMNMX+FMUL+FFMA,
// no FSETP/FSEL predicate chains (13-cyc guard latency eliminated).
__device__ __forceinline__ float sq_s(float x) {
    float t = fmaxf(fabsf(x) - 0.01f, 0.0f);
    return fmaf(-t, t, x * x);
}

__device__ __forceinline__ float voxel_contrib(
    float ux, float uy, float uz,
    float vx, float vy, float vz,
    float wx, float wy, float wz)
{
    float exy = 0.5f * (uy + vx);
    float exz = 0.5f * (uz + wx);
    float eyz = 0.5f * (vz + wy);
    float tr  = ux + vy + wz;

    float st  = sq_s(tr);
    float sxx = sq_s(ux), syy = sq_s(vy), szz = sq_s(wz);
    float sxy = sq_s(exy), sxz = sq_s(exz), syz = sq_s(eyz);

    // energy = 0.5*rt^2 + 0.5*(rxx^2+ryy^2+rzz^2) + 1.0*(rxy^2+rxz^2+ryz^2),
    // with r^2 = 0.25*s^2  ->  0.125*(st^2+sxx^2+syy^2+szz^2) + 0.25*(sxy^2+sxz^2+syz^2)
    float q1 = st * st;
    q1 = fmaf(sxx, sxx, q1);
    q1 = fmaf(syy, syy, q1);
    q1 = fmaf(szz, szz, q1);
    float q2 = sxy * sxy;
    q2 = fmaf(sxz, sxz, q2);
    q2 = fmaf(syz, syz, q2);
    float energy = fmaf(0.125f, q1, 0.25f * q2);

    // Exactly as written in the reference (NOT the textbook determinant).
    float jac = (1.0f + ux) * ((1.0f + vy) * (1.0f + wz) - vz * wy)
              - uy * (vx * (1.0f + wz) - vz * (1.0f + wx))
              + uz * (vx * wy - (1.0f + vy) * (1.0f + wx));
    return fmaf(0.1f, fmaxf(-jac, 0.0f), energy);
}

// One x-plane (4 z-voxels x 3 channels). sx is a compile-time literal at
// every call site.
__device__ __forceinline__ float plane_contrib(
    const float4 a[3], const float4 c[3], const float4 n[3],
    const float4 ymv[3], const float4 ypv[3],
    const float zmv[3], const float zpv[3],
    float sx, float sy, int zq)
{
    float4 GX[3], GY[3], GZ[3];
    #pragma unroll
    for (int ch = 0; ch < 3; ++ch) {
        const float4 cc = c[ch];
        GX[ch].x = (n[ch].x - a[ch].x) * sx;
        GX[ch].y = (n[ch].y - a[ch].y) * sx;
        GX[ch].z = (n[ch].z - a[ch].z) * sx;
        GX[ch].w = (n[ch].w - a[ch].w) * sx;

        GY[ch].x = (ypv[ch].x - ymv[ch].x) * sy;
        GY[ch].y = (ypv[ch].y - ymv[ch].y) * sy;
        GY[ch].z = (ypv[ch].z - ymv[ch].z) * sy;
        GY[ch].w = (ypv[ch].w - ymv[ch].w) * sy;

        GZ[ch].x = (zq > 0)  ? (cc.y - zmv[ch]) * 0.5f : (cc.y - cc.x);
        GZ[ch].y = (cc.z - cc.x) * 0.5f;
        GZ[ch].z = (cc.w - cc.y) * 0.5f;
        GZ[ch].w = (zq < 47) ? (zpv[ch] - cc.z) * 0.5f : (cc.w - cc.z);
    }
    float s;
    s  = voxel_contrib(GX[0].x, GY[0].x, GZ[0].x,
                       GX[1].x, GY[1].x, GZ[1].x,
                       GX[2].x, GY[2].x, GZ[2].x);
    s += voxel_contrib(GX[0].y, GY[0].y, GZ[0].y,
                       GX[1].y, GY[1].y, GZ[1].y,
                       GX[2].y, GY[2].y, GZ[2].y);
    s += voxel_contrib(GX[0].z, GY[0].z, GZ[0].z,
                       GX[1].z, GY[1].z, GZ[1].z,
                       GX[2].z, GY[2].z, GZ[2].z);
    s += voxel_contrib(GX[0].w, GY[0].w, GZ[0].w,
                       GX[1].w, GY[1].w, GZ[1].w,
                       GX[2].w, GY[2].w, GZ[2].w);
    return s;
}

__global__ __launch_bounds__(THREADS, 2)
void elastic_march(const float* __restrict__ df, float* __restrict__ out)
{
    const int tid = threadIdx.x;
    const int zq  = tid % 48;                 // z float4 group, z0 = 4*zq
    const int yy  = tid / 48;                 // 0..TYB-1
    const int y   = blockIdx.x * TYB + yy;    // 0..191
    const int xs  = blockIdx.y * SEG;
    const int b   = blockIdx.z;
    const bool first = (blockIdx.y == 0);
    const bool last  = (blockIdx.y == NXSEG - 1);

    const float sy  = (y > 0 && y < 191) ? 0.5f : 1.0f;
    const int   dym = (y > 0)   ? -NZg : 0;   // per-thread constant offsets
    const int   dyp = (y < 191) ?  NZg : 0;

    // Marching per-channel pointers at (x, y, z0); all loads are [p +/- const].
    const float* __restrict__ p0 =
        df + (size_t)b * 3 * VOLg + (size_t)xs * PLANEg + (size_t)y * NZg + 4 * zq;
    const float* pch[3] = { p0, p0 + VOLg, p0 + 2 * VOLg };

    // Software pipeline: registers hold c = plane(x), n = plane(x+1).
    float4 c[3], n[3];
    #pragma unroll
    for (int ch = 0; ch < 3; ++ch) {
        c[ch] = ld4(pch[ch]);
        n[ch] = ld4(pch[ch] + PLANEg);
    }

    float acc = 0.0f;
    int x = xs;

    // ---- prologue: x = 0 (first segment only): a == c, sx = 1 ----
    if (first) {
        float4 pf[3], ymv[3], ypv[3]; float zmv[3], zpv[3];
        #pragma unroll
        for (int ch = 0; ch < 3; ++ch) {
            pf[ch]  = ld4(pch[ch] + 2 * PLANEg);     // prefetch plane 2
            ymv[ch] = ld4(pch[ch] + dym);
            ypv[ch] = ld4(pch[ch] + dyp);
            zmv[ch] = (zq > 0)  ? pch[ch][-1] : 0.0f;
            zpv[ch] = (zq < 47) ? pch[ch][4]  : 0.0f;
        }
        acc += plane_contrib(c, c, n, ymv, ypv, zmv, zpv, 1.0f, sy, zq);
        #pragma unroll
        for (int ch = 0; ch < 3; ++ch) { c[ch] = n[ch]; n[ch] = pf[ch]; pch[ch] += PLANEg; }
        x = 1;
    }

    // ---- interior: sx = 0.5 literal; pf(x+2) issued first (DRAM latency
    //      overlapped with this plane's compute); a(x-1) reloaded from L1 ----
    const int x_end = last ? 191 : xs + SEG;
    #pragma unroll 1
    for (; x < x_end; ++x) {
        const int off2 = (x + 2 <= 191) ? 2 * PLANEg : PLANEg;  // clamp; value unused when clamped
        float4 pf[3], a[3], ymv[3], ypv[3]; float zmv[3], zpv[3];
        #pragma unroll
        for (int ch = 0; ch < 3; ++ch)
            pf[ch]  = ld4(pch[ch] + off2);           // DRAM prefetch, issued first
        #pragma unroll
        for (int ch = 0; ch < 3; ++ch) {
            a[ch]   = ld4(pch[ch] - PLANEg);         // L1 (loaded 2 iters ago)
            ymv[ch] = ld4(pch[ch] + dym);            // L1
            ypv[ch] = ld4(pch[ch] + dyp);            // L1
            zmv[ch] = (zq > 0)  ? pch[ch][-1] : 0.0f;
            zpv[ch] = (zq < 47) ? pch[ch][4]  : 0.0f;
        }
        acc += plane_contrib(a, c, n, ymv, ypv, zmv, zpv, 0.5f, sy, zq);
        #pragma unroll
        for (int ch = 0; ch < 3; ++ch) { c[ch] = n[ch]; n[ch] = pf[ch]; pch[ch] += PLANEg; }
    }

    // ---- epilogue: x = 191 (last segment only): n == c, sx = 1 ----
    if (last) {
        float4 a[3], ymv[3], ypv[3]; float zmv[3], zpv[3];
        #pragma unroll
        for (int ch = 0; ch < 3; ++ch) {
            a[ch]   = ld4(pch[ch] - PLANEg);
            ymv[ch] = ld4(pch[ch] + dym);
            ypv[ch] = ld4(pch[ch] + dyp);
            zmv[ch] = (zq > 0)  ? pch[ch][-1] : 0.0f;
            zpv[ch] = (zq < 47) ? pch[ch][4]  : 0.0f;
        }
        acc += plane_contrib(a, c, c, ymv, ypv, zmv, zpv, 1.0f, sy, zq);
    }

    // ---- block reduction: warp shuffle -> shared -> warp 0 ----
    __shared__ float  swarp[32];
    __shared__ bool   s_last;
    __shared__ double sdw[32];

    const int lane = tid & 31;
    const int wid  = tid >> 5;                 // 12 warps

    #pragma unroll
    for (int o = 16; o > 0; o >>= 1)
        acc += __shfl_xor_sync(0xffffffffu, acc, o);
    if (lane == 0) swarp[wid] = acc;
    __syncthreads();

    if (tid < 32) {
        float v = (tid < THREADS / 32) ? swarp[tid] : 0.0f;
        #pragma unroll
        for (int o = 16; o > 0; o >>= 1)
            v += __shfl_xor_sync(0xffffffffu, v, o);
        if (tid == 0) {
            const int bid = blockIdx.x + NYT * (blockIdx.y + NXSEG * blockIdx.z);
            g_partials[bid] = v;
            __threadfence();
            unsigned old = atomicAdd(&g_count, 1u);
            s_last = (old == NPART - 1);
        }
    }
    __syncthreads();

    // ---- last block: deterministic final sum in double ----
    if (s_last) {
        double d = (tid < NPART) ? (double)__ldcg(&g_partials[tid]) : 0.0;
        #pragma unroll
        for (int o = 16; o > 0; o >>= 1)
            d += __shfl_xor_sync(0xffffffffu, d, o);
        if (lane == 0) sdw[wid] = d;
        __syncthreads();
        if (tid < 32) {
            double v = (tid < THREADS / 32) ? sdw[tid] : 0.0;
            #pragma unroll
            for (int o = 16; o > 0; o >>= 1)
                v += __shfl_xor_sync(0xffffffffu, v, o);
            if (tid == 0) {
                g_count = 0;                   // reset for graph replay
                out[0] = (float)(v / NVOX);
            }
        }
    }
}

extern "C" void kernel_launch(void* const* d_in, const int* in_sizes, int n_in,
                              void* d_out, int out_size) {
    const float* df = (const float*)d_in[0];
    dim3 grid(NYT, NXSEG, 2);   // 24 x 6 x 2 = 288 blocks, ~2/SM, one wave
    elastic_march<<<grid, THREADS>>>(df, (float*)d_out);
}

// round 17
// speedup vs baseline: 1.4994x; 1.0183x over previous
#include <cuda_runtime.h>
#include <cuda_bf16.h>

#define NZg    192
#define PLANEg (192 * 192)
#define VOLg   (192 * 192 * 192)

#define TYB     8                    // y rows per block
#define THREADS (48 * TYB)           // 384
#define SEG     32                   // x planes per block
#define NXSEG   (192 / SEG)          // 6
#define NYT     (192 / TYB)          // 24
#define NPART   (NYT * NXSEG * 2)    // 288 block partials
#define NVOX    14155776.0           // 2 * 192^3

__device__ float        g_partials[NPART];
__device__ unsigned int g_count;     // zero at load; last block resets each launch

__device__ __forceinline__ float4 ld4(const float* __restrict__ p) {
    return *reinterpret_cast<const float4*>(p);
}

// s(x) = x^2 - relu(|x|-d)^2  =>  robust(x)^2 == 0.25 * s(x)^2  (exact identity:
// robust(x) = 0.5x^2 - 0.5*relu(|x|-d)^2). Branch-free: FADD+FMNMX+FMUL+FFMA.
__device__ __forceinline__ float sq_s(float x) {
    float t = fmaxf(fabsf(x) - 0.01f, 0.0f);
    return fmaf(-t, t, x * x);
}

__device__ __forceinline__ float voxel_contrib(
    float ux, float uy, float uz,
    float vx, float vy, float vz,
    float wx, float wy, float wz)
{
    float exy = 0.5f * (uy + vx);
    float exz = 0.5f * (uz + wx);
    float eyz = 0.5f * (vz + wy);
    float tr  = ux + vy + wz;

    float st  = sq_s(tr);
    float sxx = sq_s(ux), syy = sq_s(vy), szz = sq_s(wz);
    float sxy = sq_s(exy), sxz = sq_s(exz), syz = sq_s(eyz);

    // 0.125*(st^2+sxx^2+syy^2+szz^2) + 0.25*(sxy^2+sxz^2+syz^2)
    float q1 = st * st;
    q1 = fmaf(sxx, sxx, q1);
    q1 = fmaf(syy, syy, q1);
    q1 = fmaf(szz, szz, q1);
    float q2 = sxy * sxy;
    q2 = fmaf(sxz, sxz, q2);
    q2 = fmaf(syz, syz, q2);
    float energy = fmaf(0.125f, q1, 0.25f * q2);

    // Exactly as written in the reference (NOT the textbook determinant).
    float jac = (1.0f + ux) * ((1.0f + vy) * (1.0f + wz) - vz * wy)
              - uy * (vx * (1.0f + wz) - vz * (1.0f + wx))
              + uz * (vx * wy - (1.0f + vy) * (1.0f + wx));
    return fmaf(0.1f, fmaxf(-jac, 0.0f), energy);
}

// One x-plane (4 z-voxels x 3 channels). sx/sy literal at interior call sites.
__device__ __forceinline__ float plane_contrib(
    const float4 a[3], const float4 c[3], const float4 n[3],
    const float4 ymv[3], const float4 ypv[3],
    const float zmv[3], const float zpv[3],
    float sx, float sy, int zq)
{
    float4 GX[3], GY[3], GZ[3];
    #pragma unroll
    for (int ch = 0; ch < 3; ++ch) {
        const float4 cc = c[ch];
        GX[ch].x = (n[ch].x - a[ch].x) * sx;
        GX[ch].y = (n[ch].y - a[ch].y) * sx;
        GX[ch].z = (n[ch].z - a[ch].z) * sx;
        GX[ch].w = (n[ch].w - a[ch].w) * sx;

        GY[ch].x = (ypv[ch].x - ymv[ch].x) * sy;
        GY[ch].y = (ypv[ch].y - ymv[ch].y) * sy;
        GY[ch].z = (ypv[ch].z - ymv[ch].z) * sy;
        GY[ch].w = (ypv[ch].w - ymv[ch].w) * sy;

        GZ[ch].x = (zq > 0)  ? (cc.y - zmv[ch]) * 0.5f : (cc.y - cc.x);
        GZ[ch].y = (cc.z - cc.x) * 0.5f;
        GZ[ch].z = (cc.w - cc.y) * 0.5f;
        GZ[ch].w = (zq < 47) ? (zpv[ch] - cc.z) * 0.5f : (cc.w - cc.z);
    }
    float s;
    s  = voxel_contrib(GX[0].x, GY[0].x, GZ[0].x,
                       GX[1].x, GY[1].x, GZ[1].x,
                       GX[2].x, GY[2].x, GZ[2].x);
    s += voxel_contrib(GX[0].y, GY[0].y, GZ[0].y,
                       GX[1].y, GY[1].y, GZ[1].y,
                       GX[2].y, GY[2].y, GZ[2].y);
    s += voxel_contrib(GX[0].z, GY[0].z, GZ[0].z,
                       GX[1].z, GY[1].z, GZ[1].z,
                       GX[2].z, GY[2].z, GZ[2].z);
    s += voxel_contrib(GX[0].w, GY[0].w, GZ[0].w,
                       GX[1].w, GY[1].w, GZ[1].w,
                       GX[2].w, GY[2].w, GZ[2].w);
    return s;
}

// Full x-march for one thread. Inlined twice: interior-y call site passes
// literal dym/dyp/sy -> all y-halo loads become LDG-with-immediate (no IMAD);
// boundary call site passes runtime values.
__device__ __forceinline__ float march(
    const float* pu, int dym, int dyp, float sy,
    int zq, bool first, bool last, int xs)
{
    const float* pch[3] = { pu, pu + VOLg, pu + 2 * VOLg };

    // Software pipeline: registers hold c = plane(x), n = plane(x+1).
    float4 c[3], n[3];
    #pragma unroll
    for (int ch = 0; ch < 3; ++ch) {
        c[ch] = ld4(pch[ch]);
        n[ch] = ld4(pch[ch] + PLANEg);
    }

    float acc = 0.0f;
    int x = xs;

    // ---- prologue: x = 0 (first segment only): a == c, sx = 1 ----
    if (first) {
        float4 pf[3], ymv[3], ypv[3]; float zmv[3], zpv[3];
        #pragma unroll
        for (int ch = 0; ch < 3; ++ch) {
            pf[ch]  = ld4(pch[ch] + 2 * PLANEg);
            ymv[ch] = ld4(pch[ch] + dym);
            ypv[ch] = ld4(pch[ch] + dyp);
            zmv[ch] = (zq > 0)  ? pch[ch][-1] : 0.0f;
            zpv[ch] = (zq < 47) ? pch[ch][4]  : 0.0f;
        }
        acc += plane_contrib(c, c, n, ymv, ypv, zmv, zpv, 1.0f, sy, zq);
        #pragma unroll
        for (int ch = 0; ch < 3; ++ch) { c[ch] = n[ch]; n[ch] = pf[ch]; pch[ch] += PLANEg; }
        x = 1;
    }

    // ---- interior: sx = 0.5 literal; pf(x+2) at fixed immediate offset
    //      (valid through x = 189); a(x-1)/y-halo/z-halo from L1 ----
    const int x_hi = last ? 190 : xs + SEG;
    #pragma unroll 1
    for (; x < x_hi; ++x) {
        float4 pf[3], a[3], ymv[3], ypv[3]; float zmv[3], zpv[3];
        #pragma unroll
        for (int ch = 0; ch < 3; ++ch)
            pf[ch]  = ld4(pch[ch] + 2 * PLANEg);     // DRAM prefetch, issued first
        #pragma unroll
        for (int ch = 0; ch < 3; ++ch) {
            a[ch]   = ld4(pch[ch] - PLANEg);         // L1 (loaded 2 iters ago)
            ymv[ch] = ld4(pch[ch] + dym);            // L1
            ypv[ch] = ld4(pch[ch] + dyp);            // L1
            zmv[ch] = (zq > 0)  ? pch[ch][-1] : 0.0f;
            zpv[ch] = (zq < 47) ? pch[ch][4]  : 0.0f;
        }
        acc += plane_contrib(a, c, n, ymv, ypv, zmv, zpv, 0.5f, sy, zq);
        #pragma unroll
        for (int ch = 0; ch < 3; ++ch) { c[ch] = n[ch]; n[ch] = pf[ch]; pch[ch] += PLANEg; }
    }

    if (last) {
        // ---- x = 190: no prefetch needed ----
        {
            float4 a[3], ymv[3], ypv[3]; float zmv[3], zpv[3];
            #pragma unroll
            for (int ch = 0; ch < 3; ++ch) {
                a[ch]   = ld4(pch[ch] - PLANEg);
                ymv[ch] = ld4(pch[ch] + dym);
                ypv[ch] = ld4(pch[ch] + dyp);
                zmv[ch] = (zq > 0)  ? pch[ch][-1] : 0.0f;
                zpv[ch] = (zq < 47) ? pch[ch][4]  : 0.0f;
            }
            acc += plane_contrib(a, c, n, ymv, ypv, zmv, zpv, 0.5f, sy, zq);
            #pragma unroll
            for (int ch = 0; ch < 3; ++ch) { c[ch] = n[ch]; pch[ch] += PLANEg; }
        }
        // ---- epilogue: x = 191: n == c, sx = 1 ----
        {
            float4 a[3], ymv[3], ypv[3]; float zmv[3], zpv[3];
            #pragma unroll
            for (int ch = 0; ch < 3; ++ch) {
                a[ch]   = ld4(pch[ch] - PLANEg);
                ymv[ch] = ld4(pch[ch] + dym);
                ypv[ch] = ld4(pch[ch] + dyp);
                zmv[ch] = (zq > 0)  ? pch[ch][-1] : 0.0f;
                zpv[ch] = (zq < 47) ? pch[ch][4]  : 0.0f;
            }
            acc += plane_contrib(a, c, c, ymv, ypv, zmv, zpv, 1.0f, sy, zq);
        }
    }
    return acc;
}

__global__ __launch_bounds__(THREADS, 2)
void elastic_march(const float* __restrict__ df, float* __restrict__ out)
{
    const int tid = threadIdx.x;
    const int zq  = tid % 48;                 // z float4 group, z0 = 4*zq
    const int yy  = tid / 48;                 // 0..TYB-1
    const int y   = blockIdx.x * TYB + yy;    // 0..191
    const int xs  = blockIdx.y * SEG;
    const int b   = blockIdx.z;
    const bool first = (blockIdx.y == 0);
    const bool last  = (blockIdx.y == NXSEG - 1);

    const float* __restrict__ p0 =
        df + (size_t)b * 3 * VOLg + (size_t)xs * PLANEg + (size_t)y * NZg + 4 * zq;

    float acc;
    if (blockIdx.x != 0 && blockIdx.x != NYT - 1) {
        // 92% of blocks: every row is y-interior -> literal offsets & scale.
        acc = march(p0, -NZg, NZg, 0.5f, zq, first, last, xs);
    } else {
        const float sy  = (y > 0 && y < 191) ? 0.5f : 1.0f;
        const int   dym = (y > 0)   ? -NZg : 0;
        const int   dyp = (y < 191) ?  NZg : 0;
        acc = march(p0, dym, dyp, sy, zq, first, last, xs);
    }

    // ---- block reduction: warp shuffle -> shared -> warp 0 ----
    __shared__ float  swarp[32];
    __shared__ bool   s_last;
    __shared__ double sdw[32];

    const int lane = tid & 31;
    const int wid  = tid >> 5;                 // 12 warps

    #pragma unroll
    for (int o = 16; o > 0; o >>= 1)
        acc += __shfl_xor_sync(0xffffffffu, acc, o);
    if (lane == 0) swarp[wid] = acc;
    __syncthreads();

    if (tid < 32) {
        float v = (tid < THREADS / 32) ? swarp[tid] : 0.0f;
        #pragma unroll
        for (int o = 16; o > 0; o >>= 1)
            v += __shfl_xor_sync(0xffffffffu, v, o);
        if (tid == 0) {
            const int bid = blockIdx.x + NYT * (blockIdx.y + NXSEG * blockIdx.z);
            g_partials[bid] = v;
            __threadfence();
            unsigned old = atomicAdd(&g_count, 1u);
            s_last = (old == NPART - 1);
        }
    }
    __syncthreads();

    // ---- last block: deterministic final sum in double ----
    if (s_last) {
        double d = (tid < NPART) ? (double)__ldcg(&g_partials[tid]) : 0.0;
        #pragma unroll
        for (int o = 16; o > 0; o >>= 1)
            d += __shfl_xor_sync(0xffffffffu, d, o);
        if (lane == 0) sdw[wid] = d;
        __syncthreads();
        if (tid < 32) {
            double v = (tid < THREADS / 32) ? sdw[tid] : 0.0;
            #pragma unroll
            for (int o = 16; o > 0; o >>= 1)
                v += __shfl_xor_sync(0xffffffffu, v, o);
            if (tid == 0) {
                g_count = 0;                   // reset for graph replay
                out[0] = (float)(v / NVOX);
            }
        }
    }
}

extern "C" void kernel_launch(void* const* d_in, const int* in_sizes, int n_in,
                              void* d_out, int out_size) {
    const float* df = (const float*)d_in[0];
    dim3 grid(NYT, NXSEG, 2);   // 24 x 6 x 2 = 288 blocks, ~2/SM, one wave
    elastic_march<<<grid, THREADS>>>(df, (float*)d_out);
}